// round 17
// baseline (speedup 1.0000x reference)
#include <cuda_runtime.h>

#define F    13
#define MSG  32
#define HID  64
#define INE  34
#define INEP 36
#define BB   4
#define NL   20000
#define NH   100000
#define NE   800000
#define TOT_E (BB*NE)     /* 3,200,000 */
#define HALF_E (TOT_E/2)  /* 1,600,000 */
#define TOT_N (BB*NH)     /* 400,000  */
#define HALF_N (TOT_N/2)  /* 200,000  */
#define INN  45
#define INNP 48
#define FOP  16

#define EBT 64                  /* edge block threads */
#define EBLOCKS (HALF_E/EBT)    /* 25000 */
#define NBT 64                  /* node block threads */

typedef unsigned long long ull;

// 51.2 MB scatter-add scratch. .bss => zero-initialized at module load.
// Invariant: zero at every kernel_launch entry (node_kernel re-zeros after reading).
__device__ __align__(16) float g_agg[(size_t)TOT_N * MSG];

__device__ __forceinline__ ull pk(float lo, float hi) {
    ull r; asm("mov.b64 %0, {%1,%2};" : "=l"(r) : "f"(lo), "f"(hi)); return r;
}
__device__ __forceinline__ void upk(ull v, float& lo, float& hi) {
    asm("mov.b64 {%0,%1}, %2;" : "=f"(lo), "=f"(hi) : "l"(v));
}
#define FMA2(d,a,b,c) asm("fma.rn.f32x2 %0, %1, %2, %3;" : "=l"(d) : "l"(a), "l"(b), "l"(c))
#define MUL2(d,a,b)   asm("mul.rn.f32x2 %0, %1, %2;"     : "=l"(d) : "l"(a), "l"(b))
#define ADD2(d,a,b)   asm("add.rn.f32x2 %0, %1, %2;"     : "=l"(d) : "l"(a), "l"(b))

// build 34-feature edge input vector
__device__ __forceinline__ void build_in(const float* __restrict__ zs,
                                         const float* __restrict__ zt,
                                         float* in) {
#pragma unroll
    for (int i = 0; i < F; i++) in[i] = zs[i];
#pragma unroll
    for (int i = 0; i < F; i++) in[F + i] = zt[i];
    float dx = in[0] - in[13], dy = in[1] - in[14], dz = in[2] - in[15];
    in[26] = dx; in[27] = dy; in[28] = dz;
    in[29] = dx * dx + dy * dy + dz * dz;                 // squared dist (no sqrt)
    float ax = in[3], ay = in[4], az = in[5];
    float bx = in[16], by = in[17], bz = in[18];
    float cx = ay * bz - az * by;
    float cy = az * bx - ax * bz;
    float cz = ax * by - ay * bx;
    in[30] = cx; in[31] = cy; in[32] = cz;
    in[33] = sqrtf(cx * cx + cy * cy + cz * cz);
}

// 2 edges per thread (halves LDS/edge) + 64-thread blocks at occ 5
// (10 warps/SM, +25% latency hiding vs 8 at the 204-reg cap).
__global__ void __launch_bounds__(EBT, 5) edge_kernel(
    const float* __restrict__ z_l, const float* __restrict__ z_h,
    const int* __restrict__ src, const int* __restrict__ tgt,
    const float* __restrict__ We1, const float* __restrict__ be1,
    const float* __restrict__ We2, const float* __restrict__ be2,
    const float* __restrict__ Ww1, const float* __restrict__ bw1,
    const float* __restrict__ Ww2, const float* __restrict__ bw2)
{
    __shared__ __align__(16) float sWe1[HID][INEP];
    __shared__ __align__(16) float sWw1[HID][INEP];
    __shared__ __align__(16) float sWe2[HID * MSG];
    __shared__ float sWw2[HID], sbe1[HID], sbw1[HID], sbe2[MSG], sbw2;

    const int tid = threadIdx.x;

    for (int i = tid; i < INE * HID; i += EBT) {
        int k = i / HID, h = i % HID;           // We1 is (INE, HID) row-major
        sWe1[h][k] = We1[i];
        sWw1[h][k] = Ww1[i];
    }
    for (int i = tid; i < HID * MSG; i += EBT) sWe2[i] = We2[i];
    if (tid < HID) {
        sWw2[tid] = Ww2[tid];
        sbe1[tid] = be1[tid];
        sbw1[tid] = bw1[tid];
    }
    if (tid < MSG) sbe2[tid] = be2[tid];
    if (tid == 0) sbw2 = bw2[0];
    __syncthreads();

    const int eA = blockIdx.x * EBT + tid;   // [0, HALF_E)
    const int eB = eA + HALF_E;
    const int bA = eA / NE;
    const int bB = eB / NE;
    const int tA = tgt[eA];
    const int tB = tgt[eB];

    float inA[INE], inB[INE];
    build_in(z_l + ((size_t)bA * NL + src[eA]) * F,
             z_h + ((size_t)bA * NH + tA) * F, inA);
    build_in(z_l + ((size_t)bB * NL + src[eB]) * F,
             z_h + ((size_t)bB * NH + tB) * F, inB);

    ull ipA[17], ipB[17];
#pragma unroll
    for (int k = 0; k < 17; k++) {
        ipA[k] = pk(inA[2 * k], inA[2 * k + 1]);
        ipB[k] = pk(inB[2 * k], inB[2 * k + 1]);
    }

    ull mA[MSG / 2], mB[MSG / 2];
#pragma unroll
    for (int j = 0; j < MSG / 2; j++) {
        ull bij = pk(sbe2[2 * j], sbe2[2 * j + 1]);
        mA[j] = bij;
        mB[j] = bij;
    }
    float wsA = sbw2, wsB = sbw2;

#pragma unroll 1
    for (int hg = 0; hg < HID; hg += 4) {
        ull eAcc[4], eBcc[4], wAcc[4], wBcc[4];
#pragma unroll
        for (int u = 0; u < 4; u++) {
            const int h = hg + u;
            const ulonglong2* we = (const ulonglong2*)&sWe1[h][0];
            const ulonglong2* ww = (const ulonglong2*)&sWw1[h][0];
            ull ea = pk(sbe1[h], 0.f), eb = ea;
            ull wa = pk(sbw1[h], 0.f), wb = wa;
#pragma unroll
            for (int q = 0; q < 8; q++) {
                ulonglong2 W = we[q];
                ulonglong2 C = ww[q];
                FMA2(ea, W.x, ipA[2 * q],     ea);
                FMA2(eb, W.x, ipB[2 * q],     eb);
                FMA2(ea, W.y, ipA[2 * q + 1], ea);
                FMA2(eb, W.y, ipB[2 * q + 1], eb);
                FMA2(wa, C.x, ipA[2 * q],     wa);
                FMA2(wb, C.x, ipB[2 * q],     wb);
                FMA2(wa, C.y, ipA[2 * q + 1], wa);
                FMA2(wb, C.y, ipB[2 * q + 1], wb);
            }
            {   // tail pair (k = 32,33)
                ull wt = ((const ull*)&sWe1[h][0])[16];
                ull ct = ((const ull*)&sWw1[h][0])[16];
                FMA2(ea, wt, ipA[16], ea);
                FMA2(eb, wt, ipB[16], eb);
                FMA2(wa, ct, ipA[16], wa);
                FMA2(wb, ct, ipB[16], wb);
            }
            eAcc[u] = ea; eBcc[u] = eb;
            wAcc[u] = wa; wBcc[u] = wb;
        }
        float heA[4], hwA[4], heB[4], hwB[4];
#pragma unroll
        for (int u = 0; u < 4; u++) {
            float x0, x1, y0, y1;
            upk(eAcc[u], x0, x1);
            upk(wAcc[u], y0, y1);
            heA[u] = __expf(2.0f * (x0 + x1));
            hwA[u] = __expf(2.0f * (y0 + y1));
            upk(eBcc[u], x0, x1);
            upk(wBcc[u], y0, y1);
            heB[u] = __expf(2.0f * (x0 + x1));
            hwB[u] = __expf(2.0f * (y0 + y1));
        }
#pragma unroll
        for (int u = 0; u < 4; u++) {
            heA[u] = 1.0f - __fdividef(2.0f, heA[u] + 1.0f);
            hwA[u] = 1.0f - __fdividef(2.0f, hwA[u] + 1.0f);
            heB[u] = 1.0f - __fdividef(2.0f, heB[u] + 1.0f);
            hwB[u] = 1.0f - __fdividef(2.0f, hwB[u] + 1.0f);
        }
#pragma unroll
        for (int u = 0; u < 4; u++) {
            const int h = hg + u;
            ull hpA = pk(heA[u], heA[u]);
            ull hpB = pk(heB[u], heB[u]);
            const ulonglong2* w2 = (const ulonglong2*)&sWe2[h * MSG];
#pragma unroll
            for (int q = 0; q < 8; q++) {
                ulonglong2 a = w2[q];
                FMA2(mA[2 * q],     hpA, a.x, mA[2 * q]);
                FMA2(mA[2 * q + 1], hpA, a.y, mA[2 * q + 1]);
                FMA2(mB[2 * q],     hpB, a.x, mB[2 * q]);
                FMA2(mB[2 * q + 1], hpB, a.y, mB[2 * q + 1]);
            }
            float w2h = sWw2[h];
            wsA = fmaf(hwA[u], w2h, wsA);
            wsB = fmaf(hwB[u], w2h, wsB);
        }
    }

    // epilogue edge A
    {
        float w = __fdividef(1.f, 1.f + __expf(-wsA));
        ull wp = pk(w, w);
        float* aggp = g_agg + ((size_t)bA * NH + tA) * MSG;
#pragma unroll
        for (int q = 0; q < 8; q++) {
            ull v0 = mA[2 * q], v1 = mA[2 * q + 1];
            MUL2(v0, v0, wp);
            MUL2(v1, v1, wp);
            float f0, f1, f2, f3;
            upk(v0, f0, f1);
            upk(v1, f2, f3);
            asm volatile("red.global.add.v4.f32 [%0], {%1,%2,%3,%4};"
                         :: "l"(aggp + q * 4), "f"(f0), "f"(f1), "f"(f2), "f"(f3)
                         : "memory");
        }
    }
    // epilogue edge B
    {
        float w = __fdividef(1.f, 1.f + __expf(-wsB));
        ull wp = pk(w, w);
        float* aggp = g_agg + ((size_t)bB * NH + tB) * MSG;
#pragma unroll
        for (int q = 0; q < 8; q++) {
            ull v0 = mB[2 * q], v1 = mB[2 * q + 1];
            MUL2(v0, v0, wp);
            MUL2(v1, v1, wp);
            float f0, f1, f2, f3;
            upk(v0, f0, f1);
            upk(v1, f2, f3);
            asm volatile("red.global.add.v4.f32 [%0], {%1,%2,%3,%4};"
                         :: "l"(aggp + q * 4), "f"(f0), "f"(f1), "f"(f2), "f"(f3)
                         : "memory");
        }
    }
}

// 2 nodes per thread + 64-thread blocks at occ 5 (10 warps/SM).
__global__ void __launch_bounds__(NBT, 5) node_kernel(
    const float* __restrict__ z_h,
    const float* __restrict__ Wn1, const float* __restrict__ bn1,
    const float* __restrict__ Wn2, const float* __restrict__ bn2,
    float* __restrict__ out)
{
    __shared__ __align__(16) float sW1[HID][INNP];
    __shared__ __align__(16) float sW2[HID][FOP];
    __shared__ float sb1[HID];
    __shared__ __align__(16) float sb2[FOP];

    for (int i = threadIdx.x; i < HID * INNP; i += NBT) ((float*)sW1)[i] = 0.f;
    for (int i = threadIdx.x; i < HID * FOP; i += NBT)  ((float*)sW2)[i] = 0.f;
    if (threadIdx.x < FOP) sb2[threadIdx.x] = 0.f;
    __syncthreads();
    for (int i = threadIdx.x; i < INN * HID; i += NBT) {
        int k = i / HID, h = i % HID;           // Wn1 is (INN, HID)
        sW1[h][k] = Wn1[i];
    }
    for (int i = threadIdx.x; i < HID * F; i += NBT) {
        int h = i / F, j = i % F;               // Wn2 is (HID, F)
        sW2[h][j] = Wn2[i];
    }
    if (threadIdx.x < HID) sb1[threadIdx.x] = bn1[threadIdx.x];
    if (threadIdx.x < F)   sb2[threadIdx.x] = bn2[threadIdx.x];
    __syncthreads();

    const int idx = blockIdx.x * NBT + threadIdx.x;
    if (idx >= HALF_N) return;
    const int iA = idx;
    const int iB = idx + HALF_N;

    float inA[INNP], inB[INNP];
    {
        const float* zA = z_h + (size_t)iA * F;
        const float* zB = z_h + (size_t)iB * F;
#pragma unroll
        for (int i = 0; i < F; i++) { inA[i] = zA[i]; inB[i] = zB[i]; }
        float4* agA = (float4*)(g_agg + (size_t)iA * MSG);
        float4* agB = (float4*)(g_agg + (size_t)iB * MSG);
#pragma unroll
        for (int q = 0; q < 8; q++) {
            float4 vA = agA[q];
            float4 vB = agB[q];
            inA[F + 4 * q + 0] = vA.x; inA[F + 4 * q + 1] = vA.y;
            inA[F + 4 * q + 2] = vA.z; inA[F + 4 * q + 3] = vA.w;
            inB[F + 4 * q + 0] = vB.x; inB[F + 4 * q + 1] = vB.y;
            inB[F + 4 * q + 2] = vB.z; inB[F + 4 * q + 3] = vB.w;
        }
        inA[45] = 0.f; inA[46] = 0.f; inA[47] = 0.f;
        inB[45] = 0.f; inB[46] = 0.f; inB[47] = 0.f;
        // re-zero my g_agg rows so the next kernel_launch replay sees zeros
        float4 z4 = make_float4(0.f, 0.f, 0.f, 0.f);
#pragma unroll
        for (int q = 0; q < 8; q++) { agA[q] = z4; agB[q] = z4; }
    }

    ull ipA[INNP / 2], ipB[INNP / 2];
#pragma unroll
    for (int k = 0; k < INNP / 2; k++) {
        ipA[k] = pk(inA[2 * k], inA[2 * k + 1]);
        ipB[k] = pk(inB[2 * k], inB[2 * k + 1]);
    }

    ull oA[FOP / 2], oB[FOP / 2];
#pragma unroll
    for (int j = 0; j < FOP / 2; j++) {
        ull bij = pk(sb2[2 * j], sb2[2 * j + 1]);
        oA[j] = bij;
        oB[j] = bij;
    }

#pragma unroll 1
    for (int hg = 0; hg < HID; hg += 4) {
        ull accA[4], accB[4];
#pragma unroll
        for (int u = 0; u < 4; u++) {
            const int h = hg + u;
            const ulonglong2* wr = (const ulonglong2*)&sW1[h][0];
            ull a0 = pk(sb1[h], 0.f), b0 = a0;
#pragma unroll
            for (int q = 0; q < 12; q++) {
                ulonglong2 a = wr[q];
                FMA2(a0, a.x, ipA[2 * q],     a0);
                FMA2(b0, a.x, ipB[2 * q],     b0);
                FMA2(a0, a.y, ipA[2 * q + 1], a0);
                FMA2(b0, a.y, ipB[2 * q + 1], b0);
            }
            accA[u] = a0;
            accB[u] = b0;
        }
        float heA[4], heB[4];
#pragma unroll
        for (int u = 0; u < 4; u++) {
            float e0, e1;
            upk(accA[u], e0, e1);
            heA[u] = __expf(2.0f * (e0 + e1));
            upk(accB[u], e0, e1);
            heB[u] = __expf(2.0f * (e0 + e1));
        }
#pragma unroll
        for (int u = 0; u < 4; u++) {
            heA[u] = 1.0f - __fdividef(2.0f, heA[u] + 1.0f);
            heB[u] = 1.0f - __fdividef(2.0f, heB[u] + 1.0f);
        }
#pragma unroll
        for (int u = 0; u < 4; u++) {
            const int h = hg + u;
            ull hpA = pk(heA[u], heA[u]);
            ull hpB = pk(heB[u], heB[u]);
            const ulonglong2* w2 = (const ulonglong2*)&sW2[h][0];
#pragma unroll
            for (int q = 0; q < 4; q++) {
                ulonglong2 a = w2[q];
                FMA2(oA[2 * q],     hpA, a.x, oA[2 * q]);
                FMA2(oA[2 * q + 1], hpA, a.y, oA[2 * q + 1]);
                FMA2(oB[2 * q],     hpB, a.x, oB[2 * q]);
                FMA2(oB[2 * q + 1], hpB, a.y, oB[2 * q + 1]);
            }
        }
    }
    {
        float o[FOP];
#pragma unroll
        for (int j = 0; j < FOP / 2; j++) upk(oA[j], o[2 * j], o[2 * j + 1]);
        float* op = out + (size_t)iA * F;
#pragma unroll
        for (int j = 0; j < F; j++) op[j] = o[j];
    }
    {
        float o[FOP];
#pragma unroll
        for (int j = 0; j < FOP / 2; j++) upk(oB[j], o[2 * j], o[2 * j + 1]);
        float* op = out + (size_t)iB * F;
#pragma unroll
        for (int j = 0; j < F; j++) op[j] = o[j];
    }
}

extern "C" void kernel_launch(void* const* d_in, const int* in_sizes, int n_in,
                              void* d_out, int out_size)
{
    const float* z_l = (const float*)d_in[0];
    const float* z_h = (const float*)d_in[1];
    const int*   src = (const int*)d_in[2];
    const int*   tgt = (const int*)d_in[3];
    const float* We1 = (const float*)d_in[4];
    const float* be1 = (const float*)d_in[5];
    const float* We2 = (const float*)d_in[6];
    const float* be2 = (const float*)d_in[7];
    const float* Ww1 = (const float*)d_in[8];
    const float* bw1 = (const float*)d_in[9];
    const float* Ww2 = (const float*)d_in[10];
    const float* bw2 = (const float*)d_in[11];
    const float* Wn1 = (const float*)d_in[12];
    const float* bn1 = (const float*)d_in[13];
    const float* Wn2 = (const float*)d_in[14];
    const float* bn2 = (const float*)d_in[15];
    float* out = (float*)d_out;

    edge_kernel<<<EBLOCKS, EBT>>>(z_l, z_h, src, tgt,
                                  We1, be1, We2, be2,
                                  Ww1, bw1, Ww2, bw2);
    node_kernel<<<(HALF_N + NBT - 1) / NBT, NBT>>>(z_h, Wn1, bn1, Wn2, bn2, out);
}